// round 14
// baseline (speedup 1.0000x reference)
#include <cuda_runtime.h>
#include <cstdint>
#include <math.h>

#define NC 132            // 128 GEMM CTAs + 4 argmax CTAs
#define NGEMM 128
#define NT 256
#define B 32
#define H 512
#define D 256
#define T 2048
#define V 32
#define L 100
#define G3 1536
#define NGRP 4
#define GCTAS 32          // GEMM CTAs per group
#define GROWS 8           // batch rows per group
#define JSL 16            // j columns per CTA

// sR pitches (floats): row pitch 388 = 8*48 + 4, batch pitch 48 -> bank-balanced
#define SR_BP 48
#define SR_RP 388

// smem float offsets
#define OFF_W   0                          // 48 rows x 512 W_hh slice (24576)
#define OFF_HS  24576                      // 8 x 512 h stage (4096)
#define OFF_SR  28672                      // 48 x 388 partials (18624)
#define OFF_GIE 47296                      // 32 tok x 48 (1536)
#define OFF_WO  48832                      // 32 v x 16 (512)
#define OFF_HN  49344                      // 8 x 20 (160) -- float4-friendly pitch
#define OFF_TOK 49504                      // 8 tokens
#define SMEM_FLOATS 49520
#define SMEM_BYTES (SMEM_FLOATS * 4)

// ---------------- device scratch ----------------
__device__ float g_score[B * T];
__device__ float g_ctxp[4 * B * D];
__device__ float g_ctx[B * D];
__device__ float g_gie[V * G3];
__device__ float g_gic[B * G3];
__device__ float g_h[2][B * H];
__device__ float g_lp[NGRP * GROWS * V * GCTAS];   // partial logits [g][b][v][slice]
__device__ unsigned int g_tokflag[B * 32];         // stride 32: (step<<8)|tok
__device__ unsigned int g_hc[NGRP * 2 * 32];       // per-group HALF h counters (A/B)
__device__ unsigned int g_gcnt[NGRP * 32];         // per-group lp counters (argmax gate)
__device__ unsigned int g_cnt;                     // setup barrier

__global__ void reset_kernel() {
    g_cnt = 0u;
    for (int i = 0; i < NGRP; ++i) {
        g_gcnt[i * 32] = 0u;
        g_hc[(i * 2 + 0) * 32] = 0u;
        g_hc[(i * 2 + 1) * 32] = 0u;
    }
}

// setup-phase global barrier (used 5x, all NC CTAs)
__device__ __forceinline__ void gbar(unsigned int &epoch) {
    epoch++;
    __syncthreads();
    if (threadIdx.x == 0) {
        asm volatile("red.release.gpu.add.u32 [%0], %1;" :: "l"(&g_cnt), "r"(1u) : "memory");
        unsigned int target = epoch * NC, v;
        do {
            asm volatile("ld.acquire.gpu.u32 %0, [%1];" : "=r"(v) : "l"(&g_cnt) : "memory");
        } while (v < target);
    }
    __syncthreads();
}

__device__ __forceinline__ unsigned int ldacq(const unsigned int* p) {
    unsigned int v;
    asm volatile("ld.acquire.gpu.u32 %0, [%1];" : "=r"(v) : "l"(p) : "memory");
    return v;
}

extern "C" __global__ void __launch_bounds__(NT, 1) decoder_kernel(
    const float* __restrict__ enc,    // (T, B, D)
    const float* __restrict__ emb,    // (V, D)
    const float* __restrict__ W_attn, // (H+D, 1)
    const float* __restrict__ b_attn, // unused (softmax shift-invariance)
    const float* __restrict__ W_ih,   // (3H, 2D)
    const float* __restrict__ W_hh,   // (3H, H)
    const float* __restrict__ b_ih,   // (3H,)
    const float* __restrict__ b_hh,   // (3H,)
    const float* __restrict__ W_out,  // (V, H)
    const float* __restrict__ b_out,  // (V,)
    float* __restrict__ out)          // (B, L, V)
{
    extern __shared__ float sm[];
    const int tid = threadIdx.x;
    const int cta = blockIdx.x;
    unsigned epoch = 0;
    const bool gemmcta = (cta < NGEMM);
    const int g = gemmcta ? (cta >> 5) : (cta - NGEMM);  // group id
    const int sl = cta & 31;                              // j-slice within group

    // ---- persistent W_hh slice (GEMM CTAs): 48 rows (gate*16+jj) x 512, no pad ----
    if (gemmcta) {
        for (int idx = tid; idx < 48 * 512; idx += NT) {
            int r = idx >> 9, d = idx & 511;
            int gate = r >> 4, jj = r & 15;
            sm[OFF_W + idx] = W_hh[((size_t)(gate * H + sl * JSL + jj)) * H + d];
        }
    }

    // ---- P0: enc_score[b][t] = enc[t][b]·W_e ----
    {
        const float4* w4 = reinterpret_cast<const float4*>(W_attn + H);
        for (int o = cta * NT + tid; o < B * T; o += NC * NT) {
            int b = o >> 11, t = o & (T - 1);
            const float4* e4 = reinterpret_cast<const float4*>(enc + ((size_t)t * B + b) * D);
            float acc = 0.f;
#pragma unroll 8
            for (int q = 0; q < D / 4; ++q) {
                float4 ev = e4[q], wv = w4[q];
                acc += ev.x * wv.x + ev.y * wv.y + ev.z * wv.z + ev.w * wv.w;
            }
            g_score[o] = acc;
        }
    }
    gbar(epoch);

    // ---- P1: softmax rows (32 CTAs) ----
    if (cta < B) {
        float* sR = sm + OFF_SR;
        const int b = cta;
        float m = -3.4e38f;
        for (int t = tid; t < T; t += NT) m = fmaxf(m, g_score[b * T + t]);
        sR[tid] = m;
        __syncthreads();
        for (int w = NT / 2; w > 0; w >>= 1) {
            if (tid < w) sR[tid] = fmaxf(sR[tid], sR[tid + w]);
            __syncthreads();
        }
        float mx = sR[0];
        __syncthreads();
        float sum = 0.f;
        for (int t = tid; t < T; t += NT) {
            float e = expf(g_score[b * T + t] - mx);
            g_score[b * T + t] = e;
            sum += e;
        }
        sR[tid] = sum;
        __syncthreads();
        for (int w = NT / 2; w > 0; w >>= 1) {
            if (tid < w) sR[tid] += sR[tid + w];
            __syncthreads();
        }
        float inv = 1.f / sR[0];
        __syncthreads();
        for (int t = tid; t < T; t += NT) g_score[b * T + t] *= inv;
    }
    gbar(epoch);

    // ---- P2: ctx partials (128 CTAs: b x 4 t-chunks) ----
    if (cta < 128) {
        int b = cta & 31, ch = cta >> 5;
        int d = tid;
        float acc = 0.f;
        int t0 = ch * (T / 4);
#pragma unroll 4
        for (int t = t0; t < t0 + T / 4; ++t)
            acc += __ldcg(&g_score[b * T + t]) * enc[((size_t)t * B + b) * D + d];
        g_ctxp[(ch * B + b) * D + d] = acc;
    }
    gbar(epoch);

    // ---- P2b: reduce ctx; init h0, tok flags ----
    if (cta < B) {
        int b = cta, d = tid;
        float acc = 0.f;
#pragma unroll
        for (int ch = 0; ch < 4; ++ch) acc += __ldcg(&g_ctxp[(ch * B + b) * D + d]);
        g_ctx[b * D + d] = acc;
    } else if (cta == 32) {
        for (int k = tid; k < B * H / 4; k += NT)
            ((float4*)g_h[0])[k] = make_float4(0.f, 0.f, 0.f, 0.f);
    } else if (cta == 33) {
        if (tid < B) g_tokflag[tid * 32] = (1u << 8) | 1u;  // step 1, SOS
    }
    gbar(epoch);

    // ---- P3: gie / gic tables ----
    {
        for (int o = cta * NT + tid; o < (V + B) * G3; o += NC * NT) {
            if (o < V * G3) {
                int v = o / G3, k = o - v * G3;
                const float4* er = reinterpret_cast<const float4*>(emb + (size_t)v * D);
                const float4* wr = reinterpret_cast<const float4*>(W_ih + (size_t)k * (2 * D));
                float acc = 0.f;
#pragma unroll 8
                for (int q = 0; q < D / 4; ++q) {
                    float4 ev = er[q], wv = wr[q];
                    acc += ev.x * wv.x + ev.y * wv.y + ev.z * wv.z + ev.w * wv.w;
                }
                g_gie[o] = acc;
            } else {
                int o2 = o - V * G3;
                int b = o2 / G3, k = o2 - b * G3;
                const float* cr = g_ctx + b * D;
                const float4* wr = reinterpret_cast<const float4*>(W_ih + (size_t)k * (2 * D) + D);
                float acc = b_ih[k];
#pragma unroll 8
                for (int q = 0; q < D / 4; ++q) {
                    float4 wv = wr[q];
                    acc += __ldcg(&cr[q * 4 + 0]) * wv.x + __ldcg(&cr[q * 4 + 1]) * wv.y +
                           __ldcg(&cr[q * 4 + 2]) * wv.z + __ldcg(&cr[q * 4 + 3]) * wv.w;
                }
                g_gic[o2] = acc;
            }
        }
    }
    gbar(epoch);

    // =================== main loop: 4 independent groups ===================
    if (gemmcta) {
        // per-CTA tables
        for (int idx = tid; idx < 32 * 48; idx += NT) {       // gie slice [tok][gate*16+jj]
            int tk = idx / 48, r = idx - tk * 48;
            int gate = r >> 4, jj = r & 15;
            sm[OFF_GIE + idx] = __ldcg(&g_gie[tk * G3 + gate * H + sl * JSL + jj]);
        }
        for (int idx = tid; idx < V * JSL; idx += NT) {       // W_out slice
            int v = idx >> 4, jj = idx & 15;
            sm[OFF_WO + idx] = W_out[(size_t)v * H + sl * JSL + jj];
        }
        // gate constants: r,z fold gic+b_hh; n keeps i_n (gic) separate from h_n bias
        float c0 = 0.f, c1 = 0.f, c2i = 0.f, bh2 = 0.f;
        if (tid < 128) {
            int fb = tid >> 4, fjj = tid & 15;
            int j = sl * JSL + fjj, brow = g * GROWS + fb;
            c0  = __ldcg(&g_gic[brow * G3 + j]) + b_hh[j];
            c1  = __ldcg(&g_gic[brow * G3 + H + j]) + b_hh[H + j];
            c2i = __ldcg(&g_gic[brow * G3 + 2 * H + j]);
            bh2 = b_hh[2 * H + j];
        }
        __syncthreads();

        const int lane = tid & 31;         // d-slice s
        const int w = tid >> 5;            // warp: rows w*6 .. w*6+5
        unsigned int* hcA = &g_hc[(g * 2 + 0) * 32];
        unsigned int* hcB = &g_hc[(g * 2 + 1) * 32];
        unsigned int* myhc = (sl < 16) ? hcA : hcB;   // producer's half counter
        unsigned int* gcnt = &g_gcnt[g * 32];
        unsigned int* tflag = &g_tokflag[(g * GROWS) * 32];
        float* lpout = g_lp + ((g * GROWS) * V) * GCTAS + sl;
        // stage mapping (column-split halves): row srow/srow+4, f4-col scol (half A) / scol+64 (half B)
        const int srow = tid >> 6, scol = tid & 63;

        // W chunks 2+3 (d = 256..511) cached in registers for the WHOLE loop
        ulonglong2 wreg2[6], wreg3[6];
#pragma unroll
        for (int rr = 0; rr < 6; ++rr) {
            wreg2[rr] = *(const ulonglong2*)(sm + OFF_W + (w * 6 + rr) * 512 + lane * 4 + 256);
            wreg3[rr] = *(const ulonglong2*)(sm + OFF_W + (w * 6 + rr) * 512 + lane * 4 + 384);
        }

        for (int it = 1; it <= L; ++it) {
            const int src = (it - 1) & 1, dst = it & 1;
            // ---- stage: LDG half A (gated by tail poll of hcA), poll B per-warp, LDG B ----
            const float4* hs = (const float4*)(g_h[src] + (size_t)(g * GROWS) * H);
            float4* hd = (float4*)(sm + OFF_HS);
            const int i0 = srow * 128 + scol;           // rows 0-3, cols 0-255
            const int i1 = (srow + 4) * 128 + scol;     // rows 4-7, cols 0-255
            float4 ha0 = __ldcg(hs + i0);
            float4 ha1 = __ldcg(hs + i1);
            // gate half B: one acquire per warp, warp-local join
            if (lane == 0) {
                unsigned tgtB = (unsigned)(it - 1) * 16;
                while (ldacq(hcB) < tgtB) {}
            }
            __syncwarp();
            float4 hb0 = __ldcg(hs + i0 + 64);
            float4 hb1 = __ldcg(hs + i1 + 64);
            hd[i0] = ha0;
            hd[i1] = ha1;
            __syncthreads();   // S1a: half A (cols 0-255) staged

            // ---- GEMM: register tile 8b x 6rows ----
            {
                unsigned long long acc[6][8];
#pragma unroll
                for (int rr = 0; rr < 6; ++rr)
#pragma unroll
                    for (int b = 0; b < 8; ++b) acc[rr][b] = 0ULL;

                const float* hbase = sm + OFF_HS + lane * 4;
                const float* wbase = sm + OFF_W + (w * 6) * 512 + lane * 4;
                // chunk 0 (W smem, h half A)
                {
                    ulonglong2 hv[8];
#pragma unroll
                    for (int b = 0; b < 8; ++b)
                        hv[b] = *(const ulonglong2*)(hbase + b * 512);
#pragma unroll
                    for (int rr = 0; rr < 6; ++rr) {
                        ulonglong2 wv = *(const ulonglong2*)(wbase + rr * 512);
#pragma unroll
                        for (int b = 0; b < 8; ++b) {
                            asm("fma.rn.f32x2 %0, %1, %2, %0;" : "+l"(acc[rr][b]) : "l"(hv[b].x), "l"(wv.x));
                            asm("fma.rn.f32x2 %0, %1, %2, %0;" : "+l"(acc[rr][b]) : "l"(hv[b].y), "l"(wv.y));
                        }
                    }
                }
                // commit half B (disjoint columns; covered LDG latency by chunk 0)
                hd[i0 + 64] = hb0;
                hd[i1 + 64] = hb1;
                // chunk 1 (W smem, h half A)
                {
                    ulonglong2 hv[8];
#pragma unroll
                    for (int b = 0; b < 8; ++b)
                        hv[b] = *(const ulonglong2*)(hbase + b * 512 + 128);
#pragma unroll
                    for (int rr = 0; rr < 6; ++rr) {
                        ulonglong2 wv = *(const ulonglong2*)(wbase + rr * 512 + 128);
#pragma unroll
                        for (int b = 0; b < 8; ++b) {
                            asm("fma.rn.f32x2 %0, %1, %2, %0;" : "+l"(acc[rr][b]) : "l"(hv[b].x), "l"(wv.x));
                            asm("fma.rn.f32x2 %0, %1, %2, %0;" : "+l"(acc[rr][b]) : "l"(hv[b].y), "l"(wv.y));
                        }
                    }
                }
                __syncthreads();   // S1b: half B (cols 256-511) staged
                // chunk 2 (W regs)
                {
                    ulonglong2 hv[8];
#pragma unroll
                    for (int b = 0; b < 8; ++b)
                        hv[b] = *(const ulonglong2*)(hbase + b * 512 + 256);
#pragma unroll
                    for (int rr = 0; rr < 6; ++rr)
#pragma unroll
                        for (int b = 0; b < 8; ++b) {
                            asm("fma.rn.f32x2 %0, %1, %2, %0;" : "+l"(acc[rr][b]) : "l"(hv[b].x), "l"(wreg2[rr].x));
                            asm("fma.rn.f32x2 %0, %1, %2, %0;" : "+l"(acc[rr][b]) : "l"(hv[b].y), "l"(wreg2[rr].y));
                        }
                }
                // chunk 3 (W regs)
                {
                    ulonglong2 hv[8];
#pragma unroll
                    for (int b = 0; b < 8; ++b)
                        hv[b] = *(const ulonglong2*)(hbase + b * 512 + 384);
#pragma unroll
                    for (int rr = 0; rr < 6; ++rr)
#pragma unroll
                        for (int b = 0; b < 8; ++b) {
                            asm("fma.rn.f32x2 %0, %1, %2, %0;" : "+l"(acc[rr][b]) : "l"(hv[b].x), "l"(wreg3[rr].x));
                            asm("fma.rn.f32x2 %0, %1, %2, %0;" : "+l"(acc[rr][b]) : "l"(hv[b].y), "l"(wreg3[rr].y));
                        }
                }
                float* sR = sm + OFF_SR;
#pragma unroll
                for (int rr = 0; rr < 6; ++rr)
#pragma unroll
                    for (int b = 0; b < 8; ++b) {
                        unsigned long long v = acc[rr][b];
                        sR[(w * 6 + rr) * SR_RP + b * SR_BP + lane] =
                            __uint_as_float((unsigned)v) + __uint_as_float((unsigned)(v >> 32));
                    }
            }
            // fetch tokens (published by argmax CTA, or preset for it=1)
            if (tid < GROWS) {
                unsigned f;
                do { f = ldacq(tflag + tid * 32); } while ((f >> 8) != (unsigned)it);
                ((int*)(sm + OFF_TOK))[tid] = (int)(f & 255u);
            }
            __syncthreads();   // S2

            // ---- finalize (warps 0-3) -> HN + direct STG ----
            if (tid < 128) {
                const int fb = tid >> 4, fjj = tid & 15;
                const float* sR = sm + OFF_SR;
                float gr = c0, gz = c1, gn = bh2;
#pragma unroll
                for (int q = 0; q < 8; ++q) {
                    float4 p0 = *(const float4*)(sR + (0 * 16 + fjj) * SR_RP + fb * SR_BP + q * 4);
                    float4 p1 = *(const float4*)(sR + (1 * 16 + fjj) * SR_RP + fb * SR_BP + q * 4);
                    float4 p2 = *(const float4*)(sR + (2 * 16 + fjj) * SR_RP + fb * SR_BP + q * 4);
                    gr += p0.x + p0.y + p0.z + p0.w;
                    gz += p1.x + p1.y + p1.z + p1.w;
                    gn += p2.x + p2.y + p2.z + p2.w;
                }
                int tk = ((int*)(sm + OFF_TOK))[fb];
                float e0 = sm[OFF_GIE + tk * 48 + fjj];
                float e1 = sm[OFF_GIE + tk * 48 + 16 + fjj];
                float e2 = sm[OFF_GIE + tk * 48 + 32 + fjj];
                float rr = 1.f / (1.f + __expf(-(e0 + gr)));
                float zz = 1.f / (1.f + __expf(-(e1 + gz)));
                float nn = tanhf(e2 + c2i + rr * gn);   // i_n + r * h_n
                float hold = sm[OFF_HS + fb * 512 + sl * JSL + fjj];
                float hnew = (1.f - zz) * nn + zz * hold;
                sm[OFF_HN + fb * 20 + fjj] = hnew;                       // for logits warps
                __stcg(&g_h[dst][(size_t)(g * GROWS + fb) * H + sl * JSL + fjj], hnew);
                // unblock logits warps, join finalize warps, release half counter
                asm volatile("bar.arrive 1, 256;" ::: "memory");
                asm volatile("bar.sync 2, 128;" ::: "memory");
                if (tid == 0) {
                    asm volatile("red.release.gpu.add.u32 [%0], %1;" :: "l"(myhc), "r"(1u) : "memory");
                    if (it < L) {   // poll half A for NEXT step while logits warps run
                        unsigned tgt = (unsigned)it * 16;
                        while (ldacq(hcA) < tgt) {}
                    }
                }
            } else {
                // warps 4-7: wait for finalize (barrier 1), then partial logits
                asm volatile("bar.sync 1, 256;" ::: "memory");
                const int u = tid - 128;
#pragma unroll
                for (int rep = 0; rep < 2; ++rep) {
                    int item = u + rep * 128;
                    int v = item >> 3, pb = item & 7;
                    const float* hn = sm + OFF_HN + pb * 20;
                    const float* wo = sm + OFF_WO + v * 16;
                    float a = 0.f;
#pragma unroll
                    for (int jj = 0; jj < 16; ++jj) a += hn[jj] * wo[jj];
                    __stcg(lpout + (size_t)(pb * V + v) * GCTAS, a);
                }
                asm volatile("bar.sync 3, 128;" ::: "memory");
                if (tid == 128)
                    asm volatile("red.release.gpu.add.u32 [%0], %1;" :: "l"(gcnt), "r"(1u) : "memory");
            }
            __syncthreads();   // S3: joins poll + logits; next iter stages directly
        }
    } else {
        // =============== argmax CTA (one per group, 8 rows) ===============
        unsigned int* gcnt = &g_gcnt[g * 32];
        const int b = tid >> 5, lane = tid & 31, v = lane;
        const float4* lpr = (const float4*)(g_lp + (size_t)((g * GROWS + b) * V + v) * GCTAS);
        const float bo = b_out[v];
        for (int step = 1; step <= L; ++step) {
            if (tid == 0) {
                unsigned tgt = (unsigned)step * GCTAS;
                while (ldacq(gcnt) < tgt) {}
            }
            __syncthreads();
            float a = bo;
#pragma unroll
            for (int q = 0; q < 8; ++q) {
                float4 p = __ldcg(lpr + q);
                a += p.x + p.y + p.z + p.w;
            }
            out[((size_t)(g * GROWS + b) * L + (step - 1)) * V + v] = a;
            // warp argmax, first-max semantics
            float best = a;
            int bi = v;
#pragma unroll
            for (int off = 16; off; off >>= 1) {
                float ob = __shfl_down_sync(0xffffffffu, best, off);
                int oi = __shfl_down_sync(0xffffffffu, bi, off);
                if (ob > best || (ob == best && oi < bi)) { best = ob; bi = oi; }
            }
            if (lane == 0) {
                unsigned fl = ((unsigned)(step + 1) << 8) | (unsigned)bi;
                asm volatile("st.release.gpu.u32 [%0], %1;"
                             :: "l"(&g_tokflag[(g * GROWS + b) * 32]), "r"(fl) : "memory");
            }
            __syncthreads();
        }
    }
}

extern "C" void kernel_launch(void* const* d_in, const int* in_sizes, int n_in,
                              void* d_out, int out_size) {
    const float* enc    = (const float*)d_in[0];
    const float* emb    = (const float*)d_in[1];
    const float* W_attn = (const float*)d_in[2];
    const float* b_attn = (const float*)d_in[3];
    const float* W_ih   = (const float*)d_in[4];
    const float* W_hh   = (const float*)d_in[5];
    const float* b_ih   = (const float*)d_in[6];
    const float* b_hh   = (const float*)d_in[7];
    const float* W_out  = (const float*)d_in[8];
    const float* b_out  = (const float*)d_in[9];
    float* out = (float*)d_out;

    cudaFuncSetAttribute(decoder_kernel, cudaFuncAttributeMaxDynamicSharedMemorySize, SMEM_BYTES);
    reset_kernel<<<1, 1>>>();
    decoder_kernel<<<NC, NT, SMEM_BYTES>>>(enc, emb, W_attn, b_attn, W_ih, W_hh,
                                           b_ih, b_hh, W_out, b_out, out);
}

// round 15
// speedup vs baseline: 1.0025x; 1.0025x over previous
#include <cuda_runtime.h>
#include <cstdint>
#include <math.h>

#define NC 132            // 128 GEMM CTAs + 4 argmax CTAs
#define NGEMM 128
#define NT 256
#define B 32
#define H 512
#define D 256
#define T 2048
#define V 32
#define L 100
#define G3 1536
#define NGRP 4
#define GCTAS 32          // GEMM CTAs per group
#define GROWS 8           // batch rows per group
#define JSL 16            // j columns per CTA

// sR pitches (floats): row pitch 388 = 8*48 + 4, batch pitch 48 -> bank-balanced
#define SR_BP 48
#define SR_RP 388
#define HS_P 516          // stage row pitch (conflict-free scattered STS + GEMM reads)

// smem float offsets
#define OFF_W   0                          // 48 rows x 512 W_hh slice (24576)
#define OFF_HS  24576                      // 8 x 516 h stage (4128)
#define OFF_SR  28704                      // 48 x 388 partials (18624)
#define OFF_GIE 47328                      // 32 tok x 48 (1536)
#define OFF_WO  48864                      // 32 v x 16 (512)
#define OFF_HN  49376                      // 8 x 20 (160)
#define OFF_TOK 49536                      // 8 tokens
#define SMEM_FLOATS 49552
#define SMEM_BYTES (SMEM_FLOATS * 4)

// ---------------- device scratch ----------------
__device__ float g_score[B * T];
__device__ float g_ctxp[4 * B * D];
__device__ float g_ctx[B * D];
__device__ float g_gie[V * G3];
__device__ float g_gic[B * G3];
// tagged h packs: [buf][group][slice][row][6] of (h,h,h,tag)
__device__ float4 g_hp[2 * NGRP * GCTAS * GROWS * 6];
__device__ float g_lp[NGRP * GROWS * V * GCTAS];   // partial logits [g][b][v][slice]
__device__ unsigned int g_tokflag[B * 32];         // stride 32: (step<<8)|tok
__device__ unsigned int g_gcnt[NGRP * 32];         // per-group lp counters (argmax gate)
__device__ unsigned int g_cnt;                     // setup barrier

__global__ void reset_kernel() {
    if (threadIdx.x == 0) {
        g_cnt = 0u;
        for (int i = 0; i < NGRP; ++i) g_gcnt[i * 32] = 0u;
    }
    // zero all packs: buf0 => h0 = 0 with tag 0 (valid for step 1);
    // buf1 tags = 0 never match the odd tags expected from it=2 onward until written.
    const float4 z = make_float4(0.f, 0.f, 0.f, 0.f);
    for (int i = threadIdx.x; i < 2 * NGRP * GCTAS * GROWS * 6; i += blockDim.x)
        g_hp[i] = z;
}

// setup-phase global barrier (used 5x, all NC CTAs)
__device__ __forceinline__ void gbar(unsigned int &epoch) {
    epoch++;
    __syncthreads();
    if (threadIdx.x == 0) {
        asm volatile("red.release.gpu.add.u32 [%0], %1;" :: "l"(&g_cnt), "r"(1u) : "memory");
        unsigned int target = epoch * NC, v;
        do {
            asm volatile("ld.acquire.gpu.u32 %0, [%1];" : "=r"(v) : "l"(&g_cnt) : "memory");
        } while (v < target);
    }
    __syncthreads();
}

__device__ __forceinline__ unsigned int ldacq(const unsigned int* p) {
    unsigned int v;
    asm volatile("ld.acquire.gpu.u32 %0, [%1];" : "=r"(v) : "l"(p) : "memory");
    return v;
}

extern "C" __global__ void __launch_bounds__(NT, 1) decoder_kernel(
    const float* __restrict__ enc,    // (T, B, D)
    const float* __restrict__ emb,    // (V, D)
    const float* __restrict__ W_attn, // (H+D, 1)
    const float* __restrict__ b_attn, // unused (softmax shift-invariance)
    const float* __restrict__ W_ih,   // (3H, 2D)
    const float* __restrict__ W_hh,   // (3H, H)
    const float* __restrict__ b_ih,   // (3H,)
    const float* __restrict__ b_hh,   // (3H,)
    const float* __restrict__ W_out,  // (V, H)
    const float* __restrict__ b_out,  // (V,)
    float* __restrict__ out)          // (B, L, V)
{
    extern __shared__ float sm[];
    const int tid = threadIdx.x;
    const int cta = blockIdx.x;
    unsigned epoch = 0;
    const bool gemmcta = (cta < NGEMM);
    const int g = gemmcta ? (cta >> 5) : (cta - NGEMM);  // group id
    const int sl = cta & 31;                              // j-slice within group

    // ---- persistent W_hh slice (GEMM CTAs): 48 rows (gate*16+jj) x 512, no pad ----
    if (gemmcta) {
        for (int idx = tid; idx < 48 * 512; idx += NT) {
            int r = idx >> 9, d = idx & 511;
            int gate = r >> 4, jj = r & 15;
            sm[OFF_W + idx] = W_hh[((size_t)(gate * H + sl * JSL + jj)) * H + d];
        }
    }

    // ---- P0: enc_score[b][t] = enc[t][b]·W_e ----
    {
        const float4* w4 = reinterpret_cast<const float4*>(W_attn + H);
        for (int o = cta * NT + tid; o < B * T; o += NC * NT) {
            int b = o >> 11, t = o & (T - 1);
            const float4* e4 = reinterpret_cast<const float4*>(enc + ((size_t)t * B + b) * D);
            float acc = 0.f;
#pragma unroll 8
            for (int q = 0; q < D / 4; ++q) {
                float4 ev = e4[q], wv = w4[q];
                acc += ev.x * wv.x + ev.y * wv.y + ev.z * wv.z + ev.w * wv.w;
            }
            g_score[o] = acc;
        }
    }
    gbar(epoch);

    // ---- P1: softmax rows (32 CTAs) ----
    if (cta < B) {
        float* sR = sm + OFF_SR;
        const int b = cta;
        float m = -3.4e38f;
        for (int t = tid; t < T; t += NT) m = fmaxf(m, g_score[b * T + t]);
        sR[tid] = m;
        __syncthreads();
        for (int w = NT / 2; w > 0; w >>= 1) {
            if (tid < w) sR[tid] = fmaxf(sR[tid], sR[tid + w]);
            __syncthreads();
        }
        float mx = sR[0];
        __syncthreads();
        float sum = 0.f;
        for (int t = tid; t < T; t += NT) {
            float e = expf(g_score[b * T + t] - mx);
            g_score[b * T + t] = e;
            sum += e;
        }
        sR[tid] = sum;
        __syncthreads();
        for (int w = NT / 2; w > 0; w >>= 1) {
            if (tid < w) sR[tid] += sR[tid + w];
            __syncthreads();
        }
        float inv = 1.f / sR[0];
        __syncthreads();
        for (int t = tid; t < T; t += NT) g_score[b * T + t] *= inv;
    }
    gbar(epoch);

    // ---- P2: ctx partials (128 CTAs: b x 4 t-chunks) ----
    if (cta < 128) {
        int b = cta & 31, ch = cta >> 5;
        int d = tid;
        float acc = 0.f;
        int t0 = ch * (T / 4);
#pragma unroll 4
        for (int t = t0; t < t0 + T / 4; ++t)
            acc += __ldcg(&g_score[b * T + t]) * enc[((size_t)t * B + b) * D + d];
        g_ctxp[(ch * B + b) * D + d] = acc;
    }
    gbar(epoch);

    // ---- P2b: reduce ctx; init tok flags ----
    if (cta < B) {
        int b = cta, d = tid;
        float acc = 0.f;
#pragma unroll
        for (int ch = 0; ch < 4; ++ch) acc += __ldcg(&g_ctxp[(ch * B + b) * D + d]);
        g_ctx[b * D + d] = acc;
    } else if (cta == 33) {
        if (tid < B) g_tokflag[tid * 32] = (1u << 8) | 1u;  // step 1, SOS
    }
    gbar(epoch);

    // ---- P3: gie / gic tables ----
    {
        for (int o = cta * NT + tid; o < (V + B) * G3; o += NC * NT) {
            if (o < V * G3) {
                int v = o / G3, k = o - v * G3;
                const float4* er = reinterpret_cast<const float4*>(emb + (size_t)v * D);
                const float4* wr = reinterpret_cast<const float4*>(W_ih + (size_t)k * (2 * D));
                float acc = 0.f;
#pragma unroll 8
                for (int q = 0; q < D / 4; ++q) {
                    float4 ev = er[q], wv = wr[q];
                    acc += ev.x * wv.x + ev.y * wv.y + ev.z * wv.z + ev.w * wv.w;
                }
                g_gie[o] = acc;
            } else {
                int o2 = o - V * G3;
                int b = o2 / G3, k = o2 - b * G3;
                const float* cr = g_ctx + b * D;
                const float4* wr = reinterpret_cast<const float4*>(W_ih + (size_t)k * (2 * D) + D);
                float acc = b_ih[k];
#pragma unroll 8
                for (int q = 0; q < D / 4; ++q) {
                    float4 wv = wr[q];
                    acc += __ldcg(&cr[q * 4 + 0]) * wv.x + __ldcg(&cr[q * 4 + 1]) * wv.y +
                           __ldcg(&cr[q * 4 + 2]) * wv.z + __ldcg(&cr[q * 4 + 3]) * wv.w;
                }
                g_gic[o2] = acc;
            }
        }
    }
    gbar(epoch);

    // =================== main loop: 4 independent groups ===================
    if (gemmcta) {
        // per-CTA tables
        for (int idx = tid; idx < 32 * 48; idx += NT) {       // gie slice [tok][gate*16+jj]
            int tk = idx / 48, r = idx - tk * 48;
            int gate = r >> 4, jj = r & 15;
            sm[OFF_GIE + idx] = __ldcg(&g_gie[tk * G3 + gate * H + sl * JSL + jj]);
        }
        for (int idx = tid; idx < V * JSL; idx += NT) {       // W_out slice
            int v = idx >> 4, jj = idx & 15;
            sm[OFF_WO + idx] = W_out[(size_t)v * H + sl * JSL + jj];
        }
        // gate constants: r,z fold gic+b_hh; n keeps i_n (gic) separate from h_n bias
        float c0 = 0.f, c1 = 0.f, c2i = 0.f, bh2 = 0.f;
        if (tid < 128) {
            int fb = tid >> 4, fjj = tid & 15;
            int j = sl * JSL + fjj, brow = g * GROWS + fb;
            c0  = __ldcg(&g_gic[brow * G3 + j]) + b_hh[j];
            c1  = __ldcg(&g_gic[brow * G3 + H + j]) + b_hh[H + j];
            c2i = __ldcg(&g_gic[brow * G3 + 2 * H + j]);
            bh2 = b_hh[2 * H + j];
        }
        __syncthreads();

        const int lane = tid & 31;         // d-slice s
        const int w = tid >> 5;            // warp: rows w*6 .. w*6+5
        unsigned int* gcnt = &g_gcnt[g * 32];
        unsigned int* tflag = &g_tokflag[(g * GROWS) * 32];
        float* lpout = g_lp + ((g * GROWS) * V) * GCTAS + sl;
        // stage mapping: thread reads slice slr, row srow (1:1 over 32x8)
        const int slr = tid >> 3, srow = tid & 7;

        // W chunks 2+3 (d = 256..511) cached in registers for the WHOLE loop
        ulonglong2 wreg2[6], wreg3[6];
#pragma unroll
        for (int rr = 0; rr < 6; ++rr) {
            wreg2[rr] = *(const ulonglong2*)(sm + OFF_W + (w * 6 + rr) * 512 + lane * 4 + 256);
            wreg3[rr] = *(const ulonglong2*)(sm + OFF_W + (w * 6 + rr) * 512 + lane * 4 + 384);
        }

        for (int it = 1; it <= L; ++it) {
            const int src = (it - 1) & 1, dst = it & 1;
            // ---- tagged stage: poll packs (tag==it-1); data+flag in ONE L2 transaction ----
            {
                const float4* hps = g_hp +
                    (((size_t)src * NGRP + g) * GCTAS + slr) * (GROWS * 6) + srow * 6;
                const int expct = it - 1;
                float4 p0, p1, p2, p3, p4, p5;
                do { p0 = __ldcg(hps + 0); } while (__float_as_int(p0.w) != expct);
                do { p1 = __ldcg(hps + 1); } while (__float_as_int(p1.w) != expct);
                do { p2 = __ldcg(hps + 2); } while (__float_as_int(p2.w) != expct);
                do { p3 = __ldcg(hps + 3); } while (__float_as_int(p3.w) != expct);
                do { p4 = __ldcg(hps + 4); } while (__float_as_int(p4.w) != expct);
                do { p5 = __ldcg(hps + 5); } while (__float_as_int(p5.w) != expct);
                float4* hdst = (float4*)(sm + OFF_HS + srow * HS_P + slr * 16);
                hdst[0] = make_float4(p0.x, p0.y, p0.z, p1.x);
                hdst[1] = make_float4(p1.y, p1.z, p2.x, p2.y);
                hdst[2] = make_float4(p2.z, p3.x, p3.y, p3.z);
                hdst[3] = make_float4(p4.x, p4.y, p4.z, p5.x);
            }
            __syncthreads();   // S1

            // ---- GEMM: register tile 8b x 6rows, lane = contiguous d-slice ----
            {
                unsigned long long acc[6][8];
#pragma unroll
                for (int rr = 0; rr < 6; ++rr)
#pragma unroll
                    for (int b = 0; b < 8; ++b) acc[rr][b] = 0ULL;

                const float* hbase = sm + OFF_HS + lane * 4;
                const float* wbase = sm + OFF_W + (w * 6) * 512 + lane * 4;
                // chunks 0,1: W from smem
#pragma unroll
                for (int c = 0; c < 2; ++c) {
                    ulonglong2 hv[8];
#pragma unroll
                    for (int b = 0; b < 8; ++b)
                        hv[b] = *(const ulonglong2*)(hbase + b * HS_P + c * 128);
#pragma unroll
                    for (int rr = 0; rr < 6; ++rr) {
                        ulonglong2 wv = *(const ulonglong2*)(wbase + rr * 512 + c * 128);
#pragma unroll
                        for (int b = 0; b < 8; ++b) {
                            asm("fma.rn.f32x2 %0, %1, %2, %0;" : "+l"(acc[rr][b]) : "l"(hv[b].x), "l"(wv.x));
                            asm("fma.rn.f32x2 %0, %1, %2, %0;" : "+l"(acc[rr][b]) : "l"(hv[b].y), "l"(wv.y));
                        }
                    }
                }
                // chunk 2 (W regs)
                {
                    ulonglong2 hv[8];
#pragma unroll
                    for (int b = 0; b < 8; ++b)
                        hv[b] = *(const ulonglong2*)(hbase + b * HS_P + 256);
#pragma unroll
                    for (int rr = 0; rr < 6; ++rr)
#pragma unroll
                        for (int b = 0; b < 8; ++b) {
                            asm("fma.rn.f32x2 %0, %1, %2, %0;" : "+l"(acc[rr][b]) : "l"(hv[b].x), "l"(wreg2[rr].x));
                            asm("fma.rn.f32x2 %0, %1, %2, %0;" : "+l"(acc[rr][b]) : "l"(hv[b].y), "l"(wreg2[rr].y));
                        }
                }
                // chunk 3 (W regs)
                {
                    ulonglong2 hv[8];
#pragma unroll
                    for (int b = 0; b < 8; ++b)
                        hv[b] = *(const ulonglong2*)(hbase + b * HS_P + 384);
#pragma unroll
                    for (int rr = 0; rr < 6; ++rr)
#pragma unroll
                        for (int b = 0; b < 8; ++b) {
                            asm("fma.rn.f32x2 %0, %1, %2, %0;" : "+l"(acc[rr][b]) : "l"(hv[b].x), "l"(wreg3[rr].x));
                            asm("fma.rn.f32x2 %0, %1, %2, %0;" : "+l"(acc[rr][b]) : "l"(hv[b].y), "l"(wreg3[rr].y));
                        }
                }
                float* sR = sm + OFF_SR;
#pragma unroll
                for (int rr = 0; rr < 6; ++rr)
#pragma unroll
                    for (int b = 0; b < 8; ++b) {
                        unsigned long long v = acc[rr][b];
                        sR[(w * 6 + rr) * SR_RP + b * SR_BP + lane] =
                            __uint_as_float((unsigned)v) + __uint_as_float((unsigned)(v >> 32));
                    }
            }
            // fetch tokens (published by argmax CTA, or preset for it=1)
            if (tid < GROWS) {
                unsigned f;
                do { f = ldacq(tflag + tid * 32); } while ((f >> 8) != (unsigned)it);
                ((int*)(sm + OFF_TOK))[tid] = (int)(f & 255u);
            }
            __syncthreads();   // S2

            // ---- finalize (warps 0-3) -> HN; then 48 threads publish tagged packs ----
            if (tid < 128) {
                const int fb = tid >> 4, fjj = tid & 15;
                const float* sR = sm + OFF_SR;
                float gr = c0, gz = c1, gn = bh2;
#pragma unroll
                for (int q = 0; q < 8; ++q) {
                    float4 q0 = *(const float4*)(sR + (0 * 16 + fjj) * SR_RP + fb * SR_BP + q * 4);
                    float4 q1 = *(const float4*)(sR + (1 * 16 + fjj) * SR_RP + fb * SR_BP + q * 4);
                    float4 q2 = *(const float4*)(sR + (2 * 16 + fjj) * SR_RP + fb * SR_BP + q * 4);
                    gr += q0.x + q0.y + q0.z + q0.w;
                    gz += q1.x + q1.y + q1.z + q1.w;
                    gn += q2.x + q2.y + q2.z + q2.w;
                }
                int tk = ((int*)(sm + OFF_TOK))[fb];
                float e0 = sm[OFF_GIE + tk * 48 + fjj];
                float e1 = sm[OFF_GIE + tk * 48 + 16 + fjj];
                float e2 = sm[OFF_GIE + tk * 48 + 32 + fjj];
                float rr = 1.f / (1.f + __expf(-(e0 + gr)));
                float zz = 1.f / (1.f + __expf(-(e1 + gz)));
                float nn = tanhf(e2 + c2i + rr * gn);   // i_n + r * h_n
                float hold = sm[OFF_HS + fb * HS_P + sl * JSL + fjj];
                sm[OFF_HN + fb * 20 + fjj] = (1.f - zz) * nn + zz * hold;
                // unblock logits warps (non-blocking), join finalize warps
                asm volatile("bar.arrive 1, 256;" ::: "memory");
                asm volatile("bar.sync 2, 128;" ::: "memory");
                // publish 48 tagged packs (data+tag in one 16B STG each)
                if (tid < 48) {
                    const int prow = tid / 6, pk = tid - prow * 6;
                    const float* hr = sm + OFF_HN + prow * 20 + pk * 3;
                    float4 pack = make_float4(hr[0], hr[1], hr[2], __int_as_float(it));
                    float4* hpd = g_hp +
                        (((size_t)dst * NGRP + g) * GCTAS + sl) * (GROWS * 6);
                    __stcg(hpd + prow * 6 + pk, pack);
                }
            } else {
                // warps 4-7: wait for finalize (barrier 1), then partial logits
                asm volatile("bar.sync 1, 256;" ::: "memory");
                const int u = tid - 128;
#pragma unroll
                for (int rep = 0; rep < 2; ++rep) {
                    int item = u + rep * 128;
                    int v = item >> 3, pb = item & 7;
                    const float* hn = sm + OFF_HN + pb * 20;
                    const float* wo = sm + OFF_WO + v * 16;
                    float a = 0.f;
#pragma unroll
                    for (int jj = 0; jj < 16; ++jj) a += hn[jj] * wo[jj];
                    __stcg(lpout + (size_t)(pb * V + v) * GCTAS, a);
                }
                asm volatile("bar.sync 3, 128;" ::: "memory");
                if (tid == 128)
                    asm volatile("red.release.gpu.add.u32 [%0], %1;" :: "l"(gcnt), "r"(1u) : "memory");
            }
            __syncthreads();   // S3
        }
    } else {
        // =============== argmax CTA (one per group, 8 rows) ===============
        unsigned int* gcnt = &g_gcnt[g * 32];
        const int b = tid >> 5, lane = tid & 31, v = lane;
        const float4* lpr = (const float4*)(g_lp + (size_t)((g * GROWS + b) * V + v) * GCTAS);
        const float bo = b_out[v];
        for (int step = 1; step <= L; ++step) {
            if (tid == 0) {
                unsigned tgt = (unsigned)step * GCTAS;
                while (ldacq(gcnt) < tgt) {}
            }
            __syncthreads();
            float a = bo;
#pragma unroll
            for (int q = 0; q < 8; ++q) {
                float4 p = __ldcg(lpr + q);
                a += p.x + p.y + p.z + p.w;
            }
            out[((size_t)(g * GROWS + b) * L + (step - 1)) * V + v] = a;
            // warp argmax, first-max semantics
            float best = a;
            int bi = v;
#pragma unroll
            for (int off = 16; off; off >>= 1) {
                float ob = __shfl_down_sync(0xffffffffu, best, off);
                int oi = __shfl_down_sync(0xffffffffu, bi, off);
                if (ob > best || (ob == best && oi < bi)) { best = ob; bi = oi; }
            }
            if (lane == 0) {
                unsigned fl = ((unsigned)(step + 1) << 8) | (unsigned)bi;
                asm volatile("st.release.gpu.u32 [%0], %1;"
                             :: "l"(&g_tokflag[(g * GROWS + b) * 32]), "r"(fl) : "memory");
            }
            __syncthreads();
        }
    }
}

extern "C" void kernel_launch(void* const* d_in, const int* in_sizes, int n_in,
                              void* d_out, int out_size) {
    const float* enc    = (const float*)d_in[0];
    const float* emb    = (const float*)d_in[1];
    const float* W_attn = (const float*)d_in[2];
    const float* b_attn = (const float*)d_in[3];
    const float* W_ih   = (const float*)d_in[4];
    const float* W_hh   = (const float*)d_in[5];
    const float* b_ih   = (const float*)d_in[6];
    const float* b_hh   = (const float*)d_in[7];
    const float* W_out  = (const float*)d_in[8];
    const float* b_out  = (const float*)d_in[9];
    float* out = (float*)d_out;

    cudaFuncSetAttribute(decoder_kernel, cudaFuncAttributeMaxDynamicSharedMemorySize, SMEM_BYTES);
    reset_kernel<<<1, 256>>>();
    decoder_kernel<<<NC, NT, SMEM_BYTES>>>(enc, emb, W_attn, b_attn, W_ih, W_hh,
                                           b_ih, b_hh, W_out, b_out, out);
}

// round 16
// speedup vs baseline: 1.0156x; 1.0131x over previous
#include <cuda_runtime.h>
#include <cstdint>
#include <math.h>

#define NC 132            // 128 GEMM CTAs + 4 argmax CTAs
#define NGEMM 128
#define NT 256
#define B 32
#define H 512
#define D 256
#define T 2048
#define V 32
#define L 100
#define G3 1536
#define NGRP 4
#define GCTAS 32          // GEMM CTAs per group
#define GROWS 8           // batch rows per group
#define JSL 16            // j columns per CTA

// sR pitches (floats): row pitch 388 = 8*48 + 4, batch pitch 48 -> bank-balanced
#define SR_BP 48
#define SR_RP 388

// smem float offsets
#define OFF_W   0                          // 48 rows x 512 W_hh slice (24576)
#define OFF_HS  24576                      // 8 x 512 h stage (4096)
#define OFF_SR  28672                      // 48 x 388 partials (18624)
#define OFF_GIE 47296                      // 32 tok x 48 (1536)
#define OFF_WO  48832                      // 32 v x 16 (512)
#define OFF_HN  49344                      // 8 x 20 (160) -- float4-friendly pitch
#define OFF_TOK 49504                      // 8 tokens
#define SMEM_FLOATS 49520
#define SMEM_BYTES (SMEM_FLOATS * 4)

// ---------------- device scratch ----------------
__device__ float g_score[B * T];
__device__ float g_ctxp[4 * B * D];
__device__ float g_ctx[B * D];
__device__ float g_gie[V * G3];
__device__ float g_gic[B * G3];
__device__ float g_h[2][B * H];
__device__ float g_lp[NGRP * GROWS * V * GCTAS];   // partial logits [g][b][v][slice]
__device__ unsigned int g_tokflag[B * 32];         // stride 32: (step<<8)|tok
__device__ unsigned int g_hcnt[NGRP * 32];         // per-group h counters (GEMM gate)
__device__ unsigned int g_gcnt[NGRP * 32];         // per-group lp counters (argmax gate)
__device__ unsigned int g_cnt;                     // setup barrier

__global__ void reset_kernel() {
    g_cnt = 0u;
    for (int i = 0; i < NGRP; ++i) { g_gcnt[i * 32] = 0u; g_hcnt[i * 32] = 0u; }
}

// setup-phase global barrier (used 5x, all NC CTAs)
__device__ __forceinline__ void gbar(unsigned int &epoch) {
    epoch++;
    __syncthreads();
    if (threadIdx.x == 0) {
        asm volatile("red.release.gpu.add.u32 [%0], %1;" :: "l"(&g_cnt), "r"(1u) : "memory");
        unsigned int target = epoch * NC, v;
        do {
            asm volatile("ld.acquire.gpu.u32 %0, [%1];" : "=r"(v) : "l"(&g_cnt) : "memory");
        } while (v < target);
    }
    __syncthreads();
}

__device__ __forceinline__ unsigned int ldacq(const unsigned int* p) {
    unsigned int v;
    asm volatile("ld.acquire.gpu.u32 %0, [%1];" : "=r"(v) : "l"(p) : "memory");
    return v;
}

// fast gate math (error ~1e-6 rel; gate inputs empirically far from decision boundaries)
__device__ __forceinline__ float fsigmoid(float x) {
    return __fdividef(1.f, 1.f + __expf(-x));
}
__device__ __forceinline__ float ftanh(float x) {
    // tanh(x) = 2*sigmoid(2x) - 1; saturates cleanly at +/-inf, NaN-free
    return __fdividef(2.f, 1.f + __expf(-2.f * x)) - 1.f;
}

extern "C" __global__ void __launch_bounds__(NT, 1) decoder_kernel(
    const float* __restrict__ enc,    // (T, B, D)
    const float* __restrict__ emb,    // (V, D)
    const float* __restrict__ W_attn, // (H+D, 1)
    const float* __restrict__ b_attn, // unused (softmax shift-invariance)
    const float* __restrict__ W_ih,   // (3H, 2D)
    const float* __restrict__ W_hh,   // (3H, H)
    const float* __restrict__ b_ih,   // (3H,)
    const float* __restrict__ b_hh,   // (3H,)
    const float* __restrict__ W_out,  // (V, H)
    const float* __restrict__ b_out,  // (V,)
    float* __restrict__ out)          // (B, L, V)
{
    extern __shared__ float sm[];
    const int tid = threadIdx.x;
    const int cta = blockIdx.x;
    unsigned epoch = 0;
    const bool gemmcta = (cta < NGEMM);
    const int g = gemmcta ? (cta >> 5) : (cta - NGEMM);  // group id
    const int sl = cta & 31;                              // j-slice within group

    // ---- persistent W_hh slice (GEMM CTAs): 48 rows (gate*16+jj) x 512, no pad ----
    if (gemmcta) {
        for (int idx = tid; idx < 48 * 512; idx += NT) {
            int r = idx >> 9, d = idx & 511;
            int gate = r >> 4, jj = r & 15;
            sm[OFF_W + idx] = W_hh[((size_t)(gate * H + sl * JSL + jj)) * H + d];
        }
    }

    // ---- P0: enc_score[b][t] = enc[t][b]·W_e ----
    {
        const float4* w4 = reinterpret_cast<const float4*>(W_attn + H);
        for (int o = cta * NT + tid; o < B * T; o += NC * NT) {
            int b = o >> 11, t = o & (T - 1);
            const float4* e4 = reinterpret_cast<const float4*>(enc + ((size_t)t * B + b) * D);
            float acc = 0.f;
#pragma unroll 8
            for (int q = 0; q < D / 4; ++q) {
                float4 ev = e4[q], wv = w4[q];
                acc += ev.x * wv.x + ev.y * wv.y + ev.z * wv.z + ev.w * wv.w;
            }
            g_score[o] = acc;
        }
    }
    gbar(epoch);

    // ---- P1: softmax rows (32 CTAs) ----
    if (cta < B) {
        float* sR = sm + OFF_SR;
        const int b = cta;
        float m = -3.4e38f;
        for (int t = tid; t < T; t += NT) m = fmaxf(m, g_score[b * T + t]);
        sR[tid] = m;
        __syncthreads();
        for (int w = NT / 2; w > 0; w >>= 1) {
            if (tid < w) sR[tid] = fmaxf(sR[tid], sR[tid + w]);
            __syncthreads();
        }
        float mx = sR[0];
        __syncthreads();
        float sum = 0.f;
        for (int t = tid; t < T; t += NT) {
            float e = expf(g_score[b * T + t] - mx);
            g_score[b * T + t] = e;
            sum += e;
        }
        sR[tid] = sum;
        __syncthreads();
        for (int w = NT / 2; w > 0; w >>= 1) {
            if (tid < w) sR[tid] += sR[tid + w];
            __syncthreads();
        }
        float inv = 1.f / sR[0];
        __syncthreads();
        for (int t = tid; t < T; t += NT) g_score[b * T + t] *= inv;
    }
    gbar(epoch);

    // ---- P2: ctx partials (128 CTAs: b x 4 t-chunks) ----
    if (cta < 128) {
        int b = cta & 31, ch = cta >> 5;
        int d = tid;
        float acc = 0.f;
        int t0 = ch * (T / 4);
#pragma unroll 4
        for (int t = t0; t < t0 + T / 4; ++t)
            acc += __ldcg(&g_score[b * T + t]) * enc[((size_t)t * B + b) * D + d];
        g_ctxp[(ch * B + b) * D + d] = acc;
    }
    gbar(epoch);

    // ---- P2b: reduce ctx; init h0, tok flags ----
    if (cta < B) {
        int b = cta, d = tid;
        float acc = 0.f;
#pragma unroll
        for (int ch = 0; ch < 4; ++ch) acc += __ldcg(&g_ctxp[(ch * B + b) * D + d]);
        g_ctx[b * D + d] = acc;
    } else if (cta == 32) {
        for (int k = tid; k < B * H / 4; k += NT)
            ((float4*)g_h[0])[k] = make_float4(0.f, 0.f, 0.f, 0.f);
    } else if (cta == 33) {
        if (tid < B) g_tokflag[tid * 32] = (1u << 8) | 1u;  // step 1, SOS
    }
    gbar(epoch);

    // ---- P3: gie / gic tables ----
    {
        for (int o = cta * NT + tid; o < (V + B) * G3; o += NC * NT) {
            if (o < V * G3) {
                int v = o / G3, k = o - v * G3;
                const float4* er = reinterpret_cast<const float4*>(emb + (size_t)v * D);
                const float4* wr = reinterpret_cast<const float4*>(W_ih + (size_t)k * (2 * D));
                float acc = 0.f;
#pragma unroll 8
                for (int q = 0; q < D / 4; ++q) {
                    float4 ev = er[q], wv = wr[q];
                    acc += ev.x * wv.x + ev.y * wv.y + ev.z * wv.z + ev.w * wv.w;
                }
                g_gie[o] = acc;
            } else {
                int o2 = o - V * G3;
                int b = o2 / G3, k = o2 - b * G3;
                const float* cr = g_ctx + b * D;
                const float4* wr = reinterpret_cast<const float4*>(W_ih + (size_t)k * (2 * D) + D);
                float acc = b_ih[k];
#pragma unroll 8
                for (int q = 0; q < D / 4; ++q) {
                    float4 wv = wr[q];
                    acc += __ldcg(&cr[q * 4 + 0]) * wv.x + __ldcg(&cr[q * 4 + 1]) * wv.y +
                           __ldcg(&cr[q * 4 + 2]) * wv.z + __ldcg(&cr[q * 4 + 3]) * wv.w;
                }
                g_gic[o2] = acc;
            }
        }
    }
    gbar(epoch);

    // =================== main loop: 4 independent groups ===================
    if (gemmcta) {
        // per-CTA tables
        for (int idx = tid; idx < 32 * 48; idx += NT) {       // gie slice [tok][gate*16+jj]
            int tk = idx / 48, r = idx - tk * 48;
            int gate = r >> 4, jj = r & 15;
            sm[OFF_GIE + idx] = __ldcg(&g_gie[tk * G3 + gate * H + sl * JSL + jj]);
        }
        for (int idx = tid; idx < V * JSL; idx += NT) {       // W_out slice
            int v = idx >> 4, jj = idx & 15;
            sm[OFF_WO + idx] = W_out[(size_t)v * H + sl * JSL + jj];
        }
        // gate constants: r,z fold gic+b_hh; n keeps i_n (gic) separate from h_n bias
        float c0 = 0.f, c1 = 0.f, c2i = 0.f, bh2 = 0.f;
        if (tid < 128) {
            int fb = tid >> 4, fjj = tid & 15;
            int j = sl * JSL + fjj, brow = g * GROWS + fb;
            c0  = __ldcg(&g_gic[brow * G3 + j]) + b_hh[j];
            c1  = __ldcg(&g_gic[brow * G3 + H + j]) + b_hh[H + j];
            c2i = __ldcg(&g_gic[brow * G3 + 2 * H + j]);
            bh2 = b_hh[2 * H + j];
        }
        __syncthreads();

        const int lane = tid & 31;         // d-slice s
        const int w = tid >> 5;            // warp: rows w*6 .. w*6+5
        unsigned int* hcnt = &g_hcnt[g * 32];
        unsigned int* gcnt = &g_gcnt[g * 32];
        unsigned int* tflag = &g_tokflag[(g * GROWS) * 32];
        float* lpout = g_lp + ((g * GROWS) * V) * GCTAS + sl;
        // stage mapping (column-split halves): row srow/srow+4, f4-col scol/scol+64
        const int srow = tid >> 6, scol = tid & 63;

        // W chunks 2+3 (d = 256..511) cached in registers for the WHOLE loop
        ulonglong2 wreg2[6], wreg3[6];
#pragma unroll
        for (int rr = 0; rr < 6; ++rr) {
            wreg2[rr] = *(const ulonglong2*)(sm + OFF_W + (w * 6 + rr) * 512 + lane * 4 + 256);
            wreg3[rr] = *(const ulonglong2*)(sm + OFF_W + (w * 6 + rr) * 512 + lane * 4 + 384);
        }

        for (int it = 1; it <= L; ++it) {
            const int src = (it - 1) & 1, dst = it & 1;
            // ---- stage h: issue all LDGs, commit half A (cols 0-255), start GEMM early ----
            const float4* hs = (const float4*)(g_h[src] + (size_t)(g * GROWS) * H);
            float4* hd = (float4*)(sm + OFF_HS);
            float4 ha0, ha1, hb0, hb1;
            {
                int i0 = srow * 128 + scol;           // rows 0-3
                int i1 = (srow + 4) * 128 + scol;     // rows 4-7
                ha0 = __ldcg(hs + i0);       hb0 = __ldcg(hs + i0 + 64);
                ha1 = __ldcg(hs + i1);       hb1 = __ldcg(hs + i1 + 64);
                hd[i0] = ha0;
                hd[i1] = ha1;
            }
            __syncthreads();   // S1a: half A (cols 0-255) visible
            // commit half B while GEMM chunks 0-1 run (disjoint smem columns)
            {
                int i0 = srow * 128 + scol;
                int i1 = (srow + 4) * 128 + scol;
                hd[i0 + 64] = hb0;
                hd[i1 + 64] = hb1;
            }

            // ---- GEMM: register tile 8b x 6rows, lane = contiguous d-slice ----
            {
                unsigned long long acc[6][8];
#pragma unroll
                for (int rr = 0; rr < 6; ++rr)
#pragma unroll
                    for (int b = 0; b < 8; ++b) acc[rr][b] = 0ULL;

                const float* hbase = sm + OFF_HS + lane * 4;
                const float* wbase = sm + OFF_W + (w * 6) * 512 + lane * 4;
                // chunks 0,1: W from smem, h = half A
#pragma unroll
                for (int c = 0; c < 2; ++c) {
                    ulonglong2 hv[8];
#pragma unroll
                    for (int b = 0; b < 8; ++b)
                        hv[b] = *(const ulonglong2*)(hbase + b * 512 + c * 128);
#pragma unroll
                    for (int rr = 0; rr < 6; ++rr) {
                        ulonglong2 wv = *(const ulonglong2*)(wbase + rr * 512 + c * 128);
#pragma unroll
                        for (int b = 0; b < 8; ++b) {
                            asm("fma.rn.f32x2 %0, %1, %2, %0;" : "+l"(acc[rr][b]) : "l"(hv[b].x), "l"(wv.x));
                            asm("fma.rn.f32x2 %0, %1, %2, %0;" : "+l"(acc[rr][b]) : "l"(hv[b].y), "l"(wv.y));
                        }
                    }
                }
                __syncthreads();   // S1b: half B (cols 256-511) visible
                // chunk 2 (W regs)
                {
                    ulonglong2 hv[8];
#pragma unroll
                    for (int b = 0; b < 8; ++b)
                        hv[b] = *(const ulonglong2*)(hbase + b * 512 + 256);
#pragma unroll
                    for (int rr = 0; rr < 6; ++rr)
#pragma unroll
                        for (int b = 0; b < 8; ++b) {
                            asm("fma.rn.f32x2 %0, %1, %2, %0;" : "+l"(acc[rr][b]) : "l"(hv[b].x), "l"(wreg2[rr].x));
                            asm("fma.rn.f32x2 %0, %1, %2, %0;" : "+l"(acc[rr][b]) : "l"(hv[b].y), "l"(wreg2[rr].y));
                        }
                }
                // chunk 3 (W regs)
                {
                    ulonglong2 hv[8];
#pragma unroll
                    for (int b = 0; b < 8; ++b)
                        hv[b] = *(const ulonglong2*)(hbase + b * 512 + 384);
#pragma unroll
                    for (int rr = 0; rr < 6; ++rr)
#pragma unroll
                        for (int b = 0; b < 8; ++b) {
                            asm("fma.rn.f32x2 %0, %1, %2, %0;" : "+l"(acc[rr][b]) : "l"(hv[b].x), "l"(wreg3[rr].x));
                            asm("fma.rn.f32x2 %0, %1, %2, %0;" : "+l"(acc[rr][b]) : "l"(hv[b].y), "l"(wreg3[rr].y));
                        }
                }
                float* sR = sm + OFF_SR;
#pragma unroll
                for (int rr = 0; rr < 6; ++rr)
#pragma unroll
                    for (int b = 0; b < 8; ++b) {
                        unsigned long long v = acc[rr][b];
                        sR[(w * 6 + rr) * SR_RP + b * SR_BP + lane] =
                            __uint_as_float((unsigned)v) + __uint_as_float((unsigned)(v >> 32));
                    }
            }
            // fetch tokens (published by argmax CTA, or preset for it=1)
            if (tid < GROWS) {
                unsigned f;
                do { f = ldacq(tflag + tid * 32); } while ((f >> 8) != (unsigned)it);
                ((int*)(sm + OFF_TOK))[tid] = (int)(f & 255u);
            }
            __syncthreads();   // S2

            // ---- finalize (warps 0-3) -> HN + direct STG ----
            if (tid < 128) {
                const int fb = tid >> 4, fjj = tid & 15;
                const float* sR = sm + OFF_SR;
                float gr = c0, gz = c1, gn = bh2;
#pragma unroll
                for (int q = 0; q < 8; ++q) {
                    float4 p0 = *(const float4*)(sR + (0 * 16 + fjj) * SR_RP + fb * SR_BP + q * 4);
                    float4 p1 = *(const float4*)(sR + (1 * 16 + fjj) * SR_RP + fb * SR_BP + q * 4);
                    float4 p2 = *(const float4*)(sR + (2 * 16 + fjj) * SR_RP + fb * SR_BP + q * 4);
                    gr += p0.x + p0.y + p0.z + p0.w;
                    gz += p1.x + p1.y + p1.z + p1.w;
                    gn += p2.x + p2.y + p2.z + p2.w;
                }
                int tk = ((int*)(sm + OFF_TOK))[fb];
                float e0 = sm[OFF_GIE + tk * 48 + fjj];
                float e1 = sm[OFF_GIE + tk * 48 + 16 + fjj];
                float e2 = sm[OFF_GIE + tk * 48 + 32 + fjj];
                float rr = fsigmoid(e0 + gr);
                float zz = fsigmoid(e1 + gz);
                float nn = ftanh(e2 + c2i + rr * gn);   // i_n + r * h_n
                float hold = sm[OFF_HS + fb * 512 + sl * JSL + fjj];
                float hnew = (1.f - zz) * nn + zz * hold;
                sm[OFF_HN + fb * 20 + fjj] = hnew;                       // for logits warps
                __stcg(&g_h[dst][(size_t)(g * GROWS + fb) * H + sl * JSL + fjj], hnew);
                // unblock logits warps, join finalize warps, release h counter
                asm volatile("bar.arrive 1, 256;" ::: "memory");
                asm volatile("bar.sync 2, 128;" ::: "memory");
                if (tid == 0) {
                    asm volatile("red.release.gpu.add.u32 [%0], %1;" :: "l"(hcnt), "r"(1u) : "memory");
                    if (it < L) {   // poll for NEXT step while logits warps run
                        unsigned tgt = (unsigned)it * GCTAS;
                        while (ldacq(hcnt) < tgt) {}
                    }
                }
            } else {
                // warps 4-7: wait for finalize (barrier 1), then partial logits
                asm volatile("bar.sync 1, 256;" ::: "memory");
                const int u = tid - 128;
#pragma unroll
                for (int rep = 0; rep < 2; ++rep) {
                    int item = u + rep * 128;
                    int v = item >> 3, pb = item & 7;
                    const float* hn = sm + OFF_HN + pb * 20;
                    const float* wo = sm + OFF_WO + v * 16;
                    float a = 0.f;
#pragma unroll
                    for (int jj = 0; jj < 16; ++jj) a += hn[jj] * wo[jj];
                    __stcg(lpout + (size_t)(pb * V + v) * GCTAS, a);
                }
                asm volatile("bar.sync 3, 128;" ::: "memory");
                if (tid == 128)
                    asm volatile("red.release.gpu.add.u32 [%0], %1;" :: "l"(gcnt), "r"(1u) : "memory");
            }
            __syncthreads();   // S3: joins poll + logits; next iter stages directly
        }
    } else {
        // =============== argmax CTA (one per group, 8 rows) ===============
        unsigned int* gcnt = &g_gcnt[g * 32];
        const int b = tid >> 5, lane = tid & 31, v = lane;
        const float4* lpr = (const float4*)(g_lp + (size_t)((g * GROWS + b) * V + v) * GCTAS);
        const float bo = b_out[v];
        for (int step = 1; step <= L; ++step) {
            if (tid == 0) {
                unsigned tgt = (unsigned)step * GCTAS;
                while (ldacq(gcnt) < tgt) {}
            }
            __syncthreads();
            float a = bo;
#pragma unroll
            for (int q = 0; q < 8; ++q) {
                float4 p = __ldcg(lpr + q);
                a += p.x + p.y + p.z + p.w;
            }
            out[((size_t)(g * GROWS + b) * L + (step - 1)) * V + v] = a;
            // warp argmax, first-max semantics
            float best = a;
            int bi = v;
#pragma unroll
            for (int off = 16; off; off >>= 1) {
                float ob = __shfl_down_sync(0xffffffffu, best, off);
                int oi = __shfl_down_sync(0xffffffffu, bi, off);
                if (ob > best || (ob == best && oi < bi)) { best = ob; bi = oi; }
            }
            if (lane == 0) {
                unsigned fl = ((unsigned)(step + 1) << 8) | (unsigned)bi;
                asm volatile("st.release.gpu.u32 [%0], %1;"
                             :: "l"(&g_tokflag[(g * GROWS + b) * 32]), "r"(fl) : "memory");
            }
            __syncthreads();
        }
    }
}

extern "C" void kernel_launch(void* const* d_in, const int* in_sizes, int n_in,
                              void* d_out, int out_size) {
    const float* enc    = (const float*)d_in[0];
    const float* emb    = (const float*)d_in[1];
    const float* W_attn = (const float*)d_in[2];
    const float* b_attn = (const float*)d_in[3];
    const float* W_ih   = (const float*)d_in[4];
    const float* W_hh   = (const float*)d_in[5];
    const float* b_ih   = (const float*)d_in[6];
    const float* b_hh   = (const float*)d_in[7];
    const float* W_out  = (const float*)d_in[8];
    const float* b_out  = (const float*)d_in[9];
    float* out = (float*)d_out;

    cudaFuncSetAttribute(decoder_kernel, cudaFuncAttributeMaxDynamicSharedMemorySize, SMEM_BYTES);
    reset_kernel<<<1, 1>>>();
    decoder_kernel<<<NC, NT, SMEM_BYTES>>>(enc, emb, W_attn, b_attn, W_ih, W_hh,
                                           b_ih, b_hh, W_out, b_out, out);
}